// round 14
// baseline (speedup 1.0000x reference)
#include <cuda_runtime.h>
#include <math.h>

// Problem constants (match reference)
#define BATCH 4
#define NPTS  300000
#define NX_   540
#define NY_   540
#define NZ_   8
#define NV_   (NX_ * NY_ * NZ_)          // 2,332,800
#define NFEAT 5

// d_out layout (tuple flattened, all float32):
//   [0, BATCH*NV_*NFEAT)   voxel means (46,656,000)
//   [.., +BATCH*NV_)       counts       (9,331,200)
//   last 3                 shape {540, 540, 8}
#define SUMS_B   (NV_ * NFEAT)           // 11,664,000 floats per batch

// z-split halves: lin is z-major, so z in [0,4) and [4,8) are contiguous
// ranges of NV_H voxels each.
#define NZ_H     (NZ_ / 2)               // 4
#define NV_H     (NX_ * NY_ * NZ_H)      // 1,166,400 voxels per half

// Scratch: 24 B record [x,y,z,f3,f4,cnt] per voxel, HALF-batch sized.
// Two buffers of 28 MB => 56 MB live in L2. Zeroed at load; finalize restores
// zeros to dirtied records (dirty <=> cnt>0), keeping the all-zeros invariant
// across stages and graph replays.
#define REC 6
__device__ __align__(16) float g_scratch[2][(size_t)NV_H * REC];

#define THREADS       256
// Scatter: 1 point per thread, smem-staged.
#define SCAT_PTS_BLK  THREADS                                     // 256
#define SCAT_BLOCKS   ((NPTS + SCAT_PTS_BLK - 1) / SCAT_PTS_BLK)  // 1,172
#define FIN_GROUPS    (NV_H / 4)                                  // 291,600
#define FIN_BLOCKS    ((FIN_GROUPS + THREADS - 1) / THREADS)      // 1,140

// ---------------------------------------------------------------------------
__device__ __forceinline__ void red_add_v2(float* addr, float a, float b) {
    asm volatile("red.global.add.v2.f32 [%0], {%1, %2};"
                 :: "l"(addr), "f"(a), "f"(b) : "memory");
}
__device__ __forceinline__ void red_add_v4(float* addr, float a, float b,
                                           float c, float d) {
    asm volatile("red.global.add.v4.f32 [%0], {%1, %2, %3, %4};"
                 :: "l"(addr), "f"(a), "f"(b), "f"(c), "f"(d) : "memory");
}

// ---------------------------------------------------------------------------
__device__ __forceinline__ void scatter_point(float x, float y, float z,
                                              float f3, float f4,
                                              float* __restrict__ scratch,
                                              int z0) {
    // keep = all(xyz >= LO) & all(xyz <= HI), inclusive both sides
    bool keep = (x >= -54.0f) & (x <= 54.0f) &
                (y >= -54.0f) & (y <= 54.0f) &
                (z >= -5.0f)  & (z <= 3.0f);
    if (!keep) return;

    // Reference (XLA) folds /VOX into multiply by the rounded reciprocal:
    // 1/0.2f -> exactly 5.0f. Kept points have non-negative operands, so
    // truncation == floor. (Bit-exact vs reference — do not change.)
    int cz = (int)(z + 5.0f);
    cz = min(max(cz, 0), NZ_ - 1);
    if (cz < z0 || cz >= z0 + NZ_H) return;   // other half handles it

    int cx = (int)((x + 54.0f) * 5.0f);
    int cy = (int)((y + 54.0f) * 5.0f);
    cx = min(max(cx, 0), NX_ - 1);
    cy = min(max(cy, 0), NY_ - 1);

    unsigned lin = ((unsigned)(cz - z0) * NY_ + (unsigned)cy) * NX_
                 + (unsigned)cx;

    // Record at byte offset 24*lin: lin even -> 16B-aligned; lin odd -> r+2
    // is 16B-aligned. Both ops land in the same 24B record (usually 1 line).
    float* r = scratch + (size_t)lin * REC;
    if ((lin & 1) == 0) {
        red_add_v4(r + 0, x, y, z, f3);
        red_add_v2(r + 4, f4, 1.0f);
    } else {
        red_add_v2(r + 0, x, y);
        red_add_v4(r + 2, z, f3, f4, 1.0f);
    }
}

// ---------------------------------------------------------------------------
// Fused pipeline stage. When both roles are present, roles are INTERLEAVED in
// block-ID space (even = scatter, odd = fin) so every resident wave carries a
// ~50/50 mix and the latency-bound scatter overlaps the L2/DRAM-bound fin for
// the whole stage (contiguous ordering serializes them — measured R6/R13).
//   scatter(half g)    -> g_scratch[g & 1]   (REDG path, L2-resident)
//   finalize(half g-1) -> reads g_scratch[(g-1)&1], streams dense
//                         means+counts to d_out (.cs), restores zeros.
__global__ void __launch_bounds__(THREADS)
mega_kernel(const float4* __restrict__ scat_pts, int scat_buf, int scat_z0,
            int has_scat, int has_fin,
            int fin_buf, float* __restrict__ fin_out_sums,
            float* __restrict__ fin_out_cnts,
            float* __restrict__ shape_tail) {
    __shared__ float s_pts[SCAT_PTS_BLK * NFEAT];   // 5 KB

    unsigned rb;        // role-local block index
    bool is_scat;
    if (has_scat && has_fin) {
        is_scat = (blockIdx.x & 1) == 0;
        rb = blockIdx.x >> 1;
    } else {
        is_scat = has_scat;
        rb = blockIdx.x;
    }

    if (is_scat) {
        if (rb >= SCAT_BLOCKS) return;
        // ---- scatter: stage 256 points into smem (coalesced float4), then
        //      1 point per thread. LDS stride 5 words: gcd(5,32)=1 ->
        //      conflict-free. ----
        float* scratch = g_scratch[scat_buf];
        unsigned p0 = rb * SCAT_PTS_BLK;
        if (shape_tail != nullptr && p0 == 0 && threadIdx.x == 0) {
            shape_tail[0] = 540.0f;
            shape_tail[1] = 540.0f;
            shape_tail[2] = 8.0f;
        }
        unsigned npts_blk = min((unsigned)SCAT_PTS_BLK, (unsigned)NPTS - p0);
        unsigned nf4 = npts_blk * NFEAT / 4;   // integral (npts_blk%4==0)
        const float4* src = scat_pts + (size_t)rb * (SCAT_PTS_BLK * NFEAT / 4);
        for (unsigned i = threadIdx.x; i < nf4; i += THREADS)
            ((float4*)s_pts)[i] = __ldcs(src + i);
        __syncthreads();

        if (threadIdx.x < npts_blk) {
            const float* q = s_pts + threadIdx.x * NFEAT;
            scatter_point(q[0], q[1], q[2], q[3], q[4], scratch, scat_z0);
        }
        return;
    }

    // ---- finalize: one group of 4 voxels per thread = 6 float4 reads ----
    unsigned g = rb * THREADS + threadIdx.x;
    if (g >= FIN_GROUPS) return;

    float4* sr = (float4*)(g_scratch[fin_buf] + (size_t)g * 4 * REC);
    float4 q0 = sr[0], q1 = sr[1], q2 = sr[2],
           q3 = sr[3], q4 = sr[4], q5 = sr[5];

    // voxel k floats: [6k .. 6k+6) = [x,y,z,f3,f4,cnt]
    float c0 = q1.y, c1 = q2.w, c2 = q4.y, c3 = q5.w;

    float v0x = q0.x, v0y = q0.y, v0z = q0.z, v0a = q0.w, v0b = q1.x;
    float v1x = q1.z, v1y = q1.w, v1z = q2.x, v1a = q2.y, v1b = q2.z;
    float v2x = q3.x, v2y = q3.y, v2z = q3.z, v2a = q3.w, v2b = q4.x;
    float v3x = q4.z, v3y = q4.w, v3z = q5.x, v3a = q5.y, v3b = q5.z;

    // mean = sum / max(cnt, 1); cnt<=1 cases are already exact passthrough.
    if (c0 > 1.5f) { v0x = __fdiv_rn(v0x, c0); v0y = __fdiv_rn(v0y, c0);
                     v0z = __fdiv_rn(v0z, c0); v0a = __fdiv_rn(v0a, c0);
                     v0b = __fdiv_rn(v0b, c0); }
    if (c1 > 1.5f) { v1x = __fdiv_rn(v1x, c1); v1y = __fdiv_rn(v1y, c1);
                     v1z = __fdiv_rn(v1z, c1); v1a = __fdiv_rn(v1a, c1);
                     v1b = __fdiv_rn(v1b, c1); }
    if (c2 > 1.5f) { v2x = __fdiv_rn(v2x, c2); v2y = __fdiv_rn(v2y, c2);
                     v2z = __fdiv_rn(v2z, c2); v2a = __fdiv_rn(v2a, c2);
                     v2b = __fdiv_rn(v2b, c2); }
    if (c3 > 1.5f) { v3x = __fdiv_rn(v3x, c3); v3y = __fdiv_rn(v3y, c3);
                     v3z = __fdiv_rn(v3z, c3); v3a = __fdiv_rn(v3a, c3);
                     v3b = __fdiv_rn(v3b, c3); }

    // Dense streaming writes to d_out (.cs keeps them out of L2 residency):
    float4* outs = (float4*)(fin_out_sums + (size_t)g * 20);
    __stcs(outs + 0, make_float4(v0x, v0y, v0z, v0a));
    __stcs(outs + 1, make_float4(v0b, v1x, v1y, v1z));
    __stcs(outs + 2, make_float4(v1a, v1b, v2x, v2y));
    __stcs(outs + 3, make_float4(v2z, v2a, v2b, v3x));
    __stcs(outs + 4, make_float4(v3y, v3z, v3a, v3b));
    __stcs((float4*)(fin_out_cnts + (size_t)g * 4),
           make_float4(c0, c1, c2, c3));

    // Restore zeros to dirtied scratch (dirty <=> cnt > 0). Pair granularity:
    // voxels {0,1} live in q0..q2, voxels {2,3} in q3..q5.
    const float4 z4 = make_float4(0.f, 0.f, 0.f, 0.f);
    if (c0 > 0.5f || c1 > 0.5f) { sr[0] = z4; sr[1] = z4; sr[2] = z4; }
    if (c2 > 0.5f || c3 > 0.5f) { sr[3] = z4; sr[4] = z4; sr[5] = z4; }
}

// ---------------------------------------------------------------------------
extern "C" void kernel_launch(void* const* d_in, const int* in_sizes, int n_in,
                              void* d_out, int out_size) {
    const float* pts = (const float*)d_in[0];
    float* out = (float*)d_out;

    const size_t n_sums = (size_t)BATCH * SUMS_B;        // 46,656,000
    float* sums_base = out;
    float* cnts_base = out + n_sums;
    float* shape_tail = out + n_sums + (size_t)BATCH * NV_;

    const int NHALF = BATCH * 2;   // 8 half-batches, index g = b*2 + hz

    // Pipeline: stage s runs scatter(half s) and finalize(half s-1).
    for (int s = 0; s <= NHALF; s++) {
        int g_scat = s;
        int g_fin  = s - 1;
        int has_scat = (g_scat < NHALF);
        int has_fin  = (g_fin >= 0);

        unsigned grid;
        if (has_scat && has_fin)  grid = 2u * SCAT_BLOCKS;   // interleaved
        else if (has_scat)        grid = SCAT_BLOCKS;
        else                      grid = FIN_BLOCKS;

        int b_scat = g_scat / 2, hz_scat = g_scat % 2;
        int b_fin  = g_fin  / 2, hz_fin  = g_fin  % 2;

        mega_kernel<<<grid, THREADS>>>(
            has_scat ? (const float4*)(pts + (size_t)b_scat * NPTS * NFEAT)
                     : nullptr,
            has_scat ? (g_scat & 1) : 0,
            hz_scat * NZ_H,
            has_scat, has_fin,
            has_fin ? (g_fin & 1) : 0,
            has_fin ? (sums_base + (size_t)b_fin * SUMS_B
                       + (size_t)hz_fin * NV_H * NFEAT) : nullptr,
            has_fin ? (cnts_base + (size_t)b_fin * NV_
                       + (size_t)hz_fin * NV_H) : nullptr,
            (s == 0) ? shape_tail : nullptr);
    }
}